// round 11
// baseline (speedup 1.0000x reference)
#include <cuda_runtime.h>
#include <cstdint>

#define NVOX (64*64*64)        // 262144 voxels
#define NQ   (NVOX/4)          // 65536 float4 per (b,k) slab
#define BKN 28                 // 4 batches * 7 moving parts
#define CHUNKS 32              // partial-reduction chunks per (b,k)
#define RBLOCKS (7 * CHUNKS)   // 224 reduce blocks per batch
#define RED_THREADS 256
#define APPLY_THREADS 256
#define ABLOCKS (NQ / APPLY_THREADS)   // 256 apply blocks per batch

// Scratch (no allocations allowed)
__device__ float    g_partial[4 * RBLOCKS * 4];
__device__ float    g_coef[BKN * 12];     // [0..8]=M=R-I row-major, [9..11]=d
__device__ unsigned g_cnt[4] = {0,0,0,0}; // per-batch, self-resets every launch

// ---------------- helpers ----------------
__device__ __forceinline__ uint32_t smem_u32(const void* p) {
    uint32_t a;
    asm("{ .reg .u64 t; cvta.to.shared.u64 t, %1; cvt.u32.u64 %0, t; }"
        : "=r"(a) : "l"(p));
    return a;
}
__device__ __forceinline__ void cp_async16(uint32_t dst_smem, const void* src) {
    asm volatile("cp.async.cg.shared.global [%0], [%1], 16;"
                 :: "r"(dst_smem), "l"(src) : "memory");
}
__device__ __forceinline__ void pdl_trigger() {          // allow dependent grid launch
    asm volatile("griddepcontrol.launch_dependents;");
}
__device__ __forceinline__ void pdl_wait() {             // wait for predecessor grid
    asm volatile("griddepcontrol.wait;" ::: "memory");
}

// ---------------------------------------------------------------------------
// Per-batch reduce: weighted sums (sum m, m*gx, m*gy, m*gz) for 7 parts of
// batch b. LAST block folds partials -> coefficients M = R - I,
// d = p + t - R p. Triggers its dependent (apply_b) right after issuing
// its async copies. Never calls pdl_wait: it depends on nothing.
// ---------------------------------------------------------------------------
__global__ void __launch_bounds__(RED_THREADS, 6)
reduce_k(const float* __restrict__ mask, const float* __restrict__ grids,
         const float* __restrict__ trans_vec, const float* __restrict__ rot_mat,
         int b)
{
    const int k     = blockIdx.x >> 5;     // part 0..6
    const int chunk = blockIdx.x & 31;
    const int tid = threadIdx.x;

    __shared__ __align__(16) float4 buf[2048];      // 32 KB chunk
    __shared__ float ax[64], ay[64], az[64];
    __shared__ float red[8][4];
    __shared__ float fold[7][4];
    __shared__ bool  is_last;

    const float4* m4 = (const float4*)(mask + ((size_t)(b * 8 + k)) * NVOX)
                       + (size_t)chunk * 2048;

    // ---- 8 async copies per thread, all in flight immediately ----
#pragma unroll
    for (int t = 0; t < 8; ++t)
        cp_async16(smem_u32(&buf[t * RED_THREADS + tid]), &m4[t * RED_THREADS + tid]);
    asm volatile("cp.async.commit_group;" ::: "memory");

    pdl_trigger();                                   // let apply_b start

    if (tid < 64) {
        ax[tid] = grids[tid << 12];                 // gx[i,0,0]
        ay[tid] = grids[NVOX + (tid << 6)];         // gy[0,j,0]
        az[tid] = grids[2 * NVOX + tid];            // gz[0,0,k]
    }
    __syncthreads();                                 // axes ready

    asm volatile("cp.async.wait_group 0;" ::: "memory");  // own 16B slots ready

    const int vbase = chunk * (NVOX / CHUNKS);
    float s0 = 0.f, sx = 0.f, sy = 0.f, sz = 0.f;
#pragma unroll
    for (int t = 0; t < 8; ++t) {
        const int idx4 = t * RED_THREADS + tid;
        const float4 m = buf[idx4];                 // conflict-free LDS.128
        const int v  = vbase + (idx4 << 2);
        const int i  = v >> 12;
        const int j  = (v >> 6) & 63;
        const int kk = v & 63;
        const float ms = (m.x + m.y) + (m.z + m.w);
        s0 += ms;
        sx = fmaf(ax[i], ms, sx);
        sy = fmaf(ay[j], ms, sy);
        sz = fmaf(az[kk],     m.x,
             fmaf(az[kk + 1], m.y,
             fmaf(az[kk + 2], m.z,
             fmaf(az[kk + 3], m.w, sz))));
    }

    // warp tree reduce (deterministic)
#pragma unroll
    for (int off = 16; off; off >>= 1) {
        s0 += __shfl_down_sync(0xFFFFFFFFu, s0, off);
        sx += __shfl_down_sync(0xFFFFFFFFu, sx, off);
        sy += __shfl_down_sync(0xFFFFFFFFu, sy, off);
        sz += __shfl_down_sync(0xFFFFFFFFu, sz, off);
    }
    const int w = tid >> 5, l = tid & 31;
    if (l == 0) { red[w][0] = s0; red[w][1] = sx; red[w][2] = sy; red[w][3] = sz; }
    __syncthreads();
    if (tid == 0) {
        float r0 = 0.f, r1 = 0.f, r2 = 0.f, r3 = 0.f;
#pragma unroll
        for (int i = 0; i < 8; ++i) {
            r0 += red[i][0]; r1 += red[i][1]; r2 += red[i][2]; r3 += red[i][3];
        }
        float* p = g_partial + ((size_t)b * RBLOCKS + blockIdx.x) * 4;
        p[0] = r0; p[1] = r1; p[2] = r2; p[3] = r3;
        __threadfence();                                // publish partial
        const unsigned arrived = atomicAdd(&g_cnt[b], 1u);
        is_last = (arrived == RBLOCKS - 1);
        if (is_last) g_cnt[b] = 0;                      // reset for next replay
    }
    __syncthreads();
    if (!is_last) return;

    // -------- last block: fold partials -> coefficients (L2-hot) --------
    if (tid < 7 * 4) {                  // 28 threads: one (part, component) each
        const int fk   = tid >> 2;
        const int comp = tid & 3;
        const float* p = g_partial + ((size_t)b * RBLOCKS + fk * CHUNKS) * 4 + comp;
        float s = 0.f;
#pragma unroll
        for (int c = 0; c < CHUNKS; ++c)
            s += __ldcg(p + c * 4);
        fold[fk][comp] = s;
    }
    __syncthreads();
    if (tid < 7) {
        const int bk = b * 7 + tid;
        const float inv = 1.f / fold[tid][0];
        const float pv[3] = { fold[tid][1] * inv, fold[tid][2] * inv, fold[tid][3] * inv };
        const float* R = rot_mat   + bk * 9;
        const float* t = trans_vec + bk * 3;
        float* c = g_coef + bk * 12;
#pragma unroll
        for (int r = 0; r < 3; ++r) {
            const float Rp = R[r * 3] * pv[0] + R[r * 3 + 1] * pv[1] + R[r * 3 + 2] * pv[2];
            c[r * 3 + 0] = R[r * 3 + 0] - (r == 0 ? 1.f : 0.f);
            c[r * 3 + 1] = R[r * 3 + 1] - (r == 1 ? 1.f : 0.f);
            c[r * 3 + 2] = R[r * 3 + 2] - (r == 2 ? 1.f : 0.f);
            c[9 + r]     = pv[r] + t[r] - Rp;
        }
    }
    // coefficients become visible to apply_b via its griddepcontrol.wait
}

// ---------------------------------------------------------------------------
// Per-batch apply: triggers reduce_{b+1} IMMEDIATELY (no data dependency),
// prefetches its 7 mask slices + axes, then waits on reduce_b and computes
// motion[b,c,v] = sum_{k<7} mask[b,k,v] * (M_bk[c,:].g_v + d_bk[c]).
// ---------------------------------------------------------------------------
__global__ void __launch_bounds__(APPLY_THREADS, 6)
apply_k(const float* __restrict__ mask, const float* __restrict__ grids,
        float* __restrict__ out, int b)
{
    pdl_trigger();                                   // launch reduce_{b+1} NOW

    const int blk = blockIdx.x;                      // 0..255
    const int tid = threadIdx.x;

    __shared__ __align__(16) float4 sbuf[7 * 256];   // 28 KB: 7 mask slices
    __shared__ float cf[84];
    __shared__ float ay[64], az[64];

    const int idx4 = blk * APPLY_THREADS + tid;
    const float4* mb = (const float4*)mask + ((size_t)b * 8) * NQ + idx4;

    // ---- prefetch: independent of reduce_b's results ----
#pragma unroll
    for (int k = 0; k < 7; ++k)
        cp_async16(smem_u32(&sbuf[k * 256 + tid]), &mb[(size_t)k * NQ]);
    asm volatile("cp.async.commit_group;" ::: "memory");

    if (tid < 64) {
        ay[tid] = grids[NVOX + (tid << 6)];
        az[tid] = grids[2 * NVOX + tid];
    }
    const float gx = grids[(size_t)(blk >> 2) << 12];   // block-constant x-plane

    pdl_wait();                                      // reduce_b fully done

    if (tid < 84) cf[tid] = g_coef[b * 84 + tid];    // coefficients now final
    __syncthreads();                                 // cf + axes ready

    asm volatile("cp.async.wait_group 0;" ::: "memory");  // own 16B slots ready

    const int v  = idx4 << 2;
    const int j  = (v >> 6) & 63;
    const int kk = v & 63;
    const float gy = ay[j];
    const float gz[4] = { az[kk], az[kk + 1], az[kk + 2], az[kk + 3] };

    float mot[3][4] = {};
#pragma unroll
    for (int k = 0; k < 7; ++k) {
        const float4 m = sbuf[k * 256 + tid];
        const float mvv[4] = { m.x, m.y, m.z, m.w };
        const float* c = cf + k * 12;
#pragma unroll
        for (int cc = 0; cc < 3; ++cc) {
            const float m2   = c[cc * 3 + 2];
            const float base = fmaf(c[cc * 3], gx, fmaf(c[cc * 3 + 1], gy, c[9 + cc]));
#pragma unroll
            for (int t = 0; t < 4; ++t)
                mot[cc][t] = fmaf(mvv[t], fmaf(m2, gz[t], base), mot[cc][t]);
        }
    }

    float4* o4 = (float4*)out;
#pragma unroll
    for (int cc = 0; cc < 3; ++cc) {
        float4 o = { mot[cc][0], mot[cc][1], mot[cc][2], mot[cc][3] };
        o4[((size_t)b * 3 + cc) * NQ + idx4] = o;
    }
}

// ---------------------------------------------------------------------------
// Chain: r0, a0, r1, a1, r2, a2, r3, a3 — every kernel after the first is a
// PDL secondary of its predecessor. apply_b triggers at entry, so reduce_{b+1}
// runs concurrently with apply_b; apply_b gates its compute on reduce_b only.
// ---------------------------------------------------------------------------
extern "C" void kernel_launch(void* const* d_in, const int* in_sizes, int n_in,
                              void* d_out, int out_size)
{
    const float* mask = nullptr;
    const float* tv   = nullptr;
    const float* rm   = nullptr;
    const float* gr   = nullptr;
    for (int i = 0; i < n_in; ++i) {
        switch (in_sizes[i]) {
            case 8388608: mask = (const float*)d_in[i]; break;   // (4,8,64,64,64)
            case 84:      tv   = (const float*)d_in[i]; break;   // (4,7,3)
            case 252:     rm   = (const float*)d_in[i]; break;   // (4,7,3,3)
            case 786432:  gr   = (const float*)d_in[i]; break;   // (3,64,64,64)
        }
    }

    cudaLaunchAttribute attr[1];
    attr[0].id = cudaLaunchAttributeProgrammaticStreamSerialization;
    attr[0].val.programmaticStreamSerializationAllowed = 1;

    cudaLaunchConfig_t rcfg = {};
    rcfg.gridDim  = dim3(RBLOCKS, 1, 1);
    rcfg.blockDim = dim3(RED_THREADS, 1, 1);
    rcfg.stream = 0;
    rcfg.attrs = attr;
    rcfg.numAttrs = 1;

    cudaLaunchConfig_t acfg = {};
    acfg.gridDim  = dim3(ABLOCKS, 1, 1);
    acfg.blockDim = dim3(APPLY_THREADS, 1, 1);
    acfg.stream = 0;
    acfg.attrs = attr;
    acfg.numAttrs = 1;

    // r0: plain launch (no predecessor)
    reduce_k<<<RBLOCKS, RED_THREADS>>>(mask, gr, tv, rm, 0);
    for (int b = 0; b < 4; ++b) {
        cudaLaunchKernelEx(&acfg, apply_k, mask, gr, (float*)d_out, b);
        if (b < 3)
            cudaLaunchKernelEx(&rcfg, reduce_k, mask, gr, tv, rm, b + 1);
    }
}